// round 4
// baseline (speedup 1.0000x reference)
#include <cuda_runtime.h>
#include <cuda_bf16.h>

#define H 1024
#define V 32000
#define L 64
#define E 3
#define EOS_TOK 1
#define NB2 2000   // k_out blocks (16 rows each)

// ---------------- device scratch (no allocations allowed) ----------------
__device__ __align__(16) float g_X[E * L * H];        // gathered encoder inputs
__device__ float g_gi[E * L * 3 * H];                 // precomputed W_ih @ x + b_ih
__device__ float g_outs[E * L * H];                   // per-encoder outputs (= hidden chain)
__device__ __align__(16) float g_zero[H];             // stays zero (module init)
__device__ float g_encouts[L * H];                    // combined encoder outputs
__device__ __align__(16) float g_dech[H];             // decoder hidden
__device__ __align__(16) float g_h2[H];               // candidate next hidden
__device__ float g_awraw[L];                          // raw attention logits
__device__ __align__(16) float g_applied[H];          // attention-applied context
__device__ __align__(16) float g_xvec[H];             // decoder GRU input
__device__ float g_raw[V];                            // raw output logits (bf16-weight path)
__device__ float g_blocksum2[NB2];                    // partial sum of exp per block
__device__ float g_blockcmax[NB2];                    // max raw per block
__device__ float g_blockabs[NB2];                     // max sum|w||h| per block
__device__ __align__(16) __nv_bfloat16 g_Wbf[(size_t)V * H];  // bf16 copy of W_out
__device__ int g_tok;
__device__ int g_done;
__device__ float g_logZ;

// ---------------- helpers ----------------
__device__ __forceinline__ float sigmoidf_(float x) { return 1.0f / (1.0f + expf(-x)); }

__device__ __forceinline__ float wred(float s) {
    #pragma unroll
    for (int o = 16; o; o >>= 1) s += __shfl_down_sync(0xffffffffu, s, o);
    return s;
}

// warp-collective dot product; n multiple of 128; result valid on lane 0
__device__ __forceinline__ float warp_dot(const float* __restrict__ a,
                                          const float* __restrict__ b, int n) {
    int lane = threadIdx.x & 31;
    const float4* a4 = (const float4*)a;
    const float4* b4 = (const float4*)b;
    int n4 = n >> 2;
    float s = 0.0f;
    #pragma unroll 8
    for (int i = lane; i < n4; i += 32) {
        float4 x = a4[i], y = b4[i];
        s += x.x * y.x + x.y * y.y + x.z * y.z + x.w * y.w;
    }
    return wred(s);
}

__device__ __forceinline__ unsigned f2mono(float x) {
    unsigned u = __float_as_uint(x);
    return (u & 0x80000000u) ? ~u : (u | 0x80000000u);
}

// ---------------- init ----------------
__global__ void k_init() {
    int i = threadIdx.x;
    if (i < H) g_dech[i] = 0.0f;
    if (i == 0) { g_tok = 0; g_done = 0; }
}

// ---------------- convert W_out to bf16 (once per launch) ----------------
__global__ void k_prep(const float* __restrict__ W) {
    size_t i8 = ((size_t)blockIdx.x * 256 + threadIdx.x) * 8;
    const float4* W4 = (const float4*)W;
    float4 a = W4[i8 >> 2], b = W4[(i8 >> 2) + 1];
    __nv_bfloat16 tmp[8];
    tmp[0] = __float2bfloat16_rn(a.x); tmp[1] = __float2bfloat16_rn(a.y);
    tmp[2] = __float2bfloat16_rn(a.z); tmp[3] = __float2bfloat16_rn(a.w);
    tmp[4] = __float2bfloat16_rn(b.x); tmp[5] = __float2bfloat16_rn(b.y);
    tmp[6] = __float2bfloat16_rn(b.z); tmp[7] = __float2bfloat16_rn(b.w);
    *(uint4*)(g_Wbf + i8) = *(uint4*)tmp;
}

// ---------------- encoder: gather embeddings ----------------
__global__ void k_gather(const int* __restrict__ qids, const int* __restrict__ cids,
                         const float* __restrict__ emb) {
    int e = blockIdx.x / L, t = blockIdx.x % L;
    int id = (e == 0) ? qids[t] : cids[(e - 1) * L + t];
    const float* src = emb + ((long long)e * V + id) * H;
    float* dst = g_X + (e * L + t) * H;
    for (int j = threadIdx.x; j < H; j += blockDim.x) dst[j] = src[j];
}

// ---------------- encoder: gi = W_ih @ X + b_ih for all steps (tiled GEMM) ----
__global__ void k_gi(const float* __restrict__ W, const float* __restrict__ b) {
    __shared__ float Ws[16][65];
    __shared__ float Xs[64][65];
    int e = blockIdx.x / 192, rb = blockIdx.x % 192;
    int row0 = rb * 16;
    const float* Wb = W + ((long long)e * 3 * H + row0) * H;
    const float* Xb = g_X + e * L * H;
    float acc[4] = {0.f, 0.f, 0.f, 0.f};
    int r = threadIdx.x & 15;
    int tb = threadIdx.x >> 4;   // 0..15
    for (int kt = 0; kt < 16; kt++) {
        for (int i = threadIdx.x; i < 16 * 64; i += 256)
            Ws[i >> 6][i & 63] = Wb[(long long)(i >> 6) * H + kt * 64 + (i & 63)];
        for (int i = threadIdx.x; i < 64 * 64; i += 256)
            Xs[i >> 6][i & 63] = Xb[(i >> 6) * H + kt * 64 + (i & 63)];
        __syncthreads();
        #pragma unroll
        for (int k = 0; k < 64; k++) {
            float w = Ws[r][k];
            acc[0] += w * Xs[tb][k];
            acc[1] += w * Xs[tb + 16][k];
            acc[2] += w * Xs[tb + 32][k];
            acc[3] += w * Xs[tb + 48][k];
        }
        __syncthreads();
    }
    float bias = b[e * 3 * H + row0 + r];
    #pragma unroll
    for (int i = 0; i < 4; i++) {
        int t = tb + i * 16;
        g_gi[(e * L + t) * 3 * H + row0 + r] = acc[i] + bias;
    }
}

// ---------------- encoder: one recurrent step (3 interleaved row-dots) ----
__global__ void k_enc_step(const float* __restrict__ W_hh, const float* __restrict__ b_hh, int t) {
    int e = blockIdx.x >> 7;
    int hi = ((blockIdx.x & 127) << 3) + (threadIdx.x >> 5);
    int lane = threadIdx.x & 31;
    const float* hin = (t == 0) ? g_zero : (g_outs + (e * L + t - 1) * H);
    const float4* h4 = (const float4*)hin;
    const float* W = W_hh + (long long)e * 3 * H * H;
    const float4* r0 = (const float4*)(W + (long long)hi * H);
    const float4* r1 = (const float4*)(W + (long long)(H + hi) * H);
    const float4* r2 = (const float4*)(W + (long long)(2 * H + hi) * H);
    float a0 = 0.f, a1 = 0.f, a2 = 0.f;
    #pragma unroll
    for (int i = 0; i < 8; i++) {
        int j = i * 32 + lane;
        float4 hv = h4[j];
        float4 w0 = r0[j], w1 = r1[j], w2 = r2[j];
        a0 += w0.x * hv.x + w0.y * hv.y + w0.z * hv.z + w0.w * hv.w;
        a1 += w1.x * hv.x + w1.y * hv.y + w1.z * hv.z + w1.w * hv.w;
        a2 += w2.x * hv.x + w2.y * hv.y + w2.z * hv.z + w2.w * hv.w;
    }
    a0 = wred(a0); a1 = wred(a1); a2 = wred(a2);
    if (lane == 0) {
        const float* gi = g_gi + (e * L + t) * 3 * H;
        const float* bh = b_hh + e * 3 * H;
        float r = sigmoidf_(gi[hi] + a0 + bh[hi]);
        float z = sigmoidf_(gi[H + hi] + a1 + bh[H + hi]);
        float n = tanhf(gi[2 * H + hi] + r * (a2 + bh[2 * H + hi]));
        g_outs[(e * L + t) * H + hi] = (1.0f - z) * n + z * hin[hi];
    }
}

// ---------------- encoder: ensemble combine ----------------
__global__ void k_combine() {
    int i = blockIdx.x * 256 + threadIdx.x;   // 64*1024 total
    g_encouts[i] = g_outs[i] + 0.5f * (g_outs[L * H + i] + g_outs[2 * L * H + i]);
}

// ---------------- decoder: attention logits ----------------
__global__ void k_attn(const float* __restrict__ dec_emb, const float* __restrict__ W_attn,
                       const float* __restrict__ b_attn) {
    int l = blockIdx.x * 8 + (threadIdx.x >> 5);   // 8 blocks x 8 warps = 64
    int tok = g_tok;
    const float* e = dec_emb + (long long)tok * H;
    const float* Wr = W_attn + l * 2 * H;
    float s = warp_dot(Wr, e, H);
    float s2 = warp_dot(Wr + H, g_dech, H);
    if ((threadIdx.x & 31) == 0) g_awraw[l] = s + s2 + b_attn[l];
}

// ---------------- decoder: softmax + applied context ----------------
__global__ void k_apply(float* __restrict__ attns_out, int t) {
    __shared__ float raw[L];
    __shared__ float aw[L];
    if (threadIdx.x < L) raw[threadIdx.x] = g_awraw[threadIdx.x];
    __syncthreads();
    float m = -3.0e38f;
    for (int l = 0; l < L; l++) m = fmaxf(m, raw[l]);
    float ss = 0.0f;
    for (int l = 0; l < L; l++) ss += expf(raw[l] - m);
    if (threadIdx.x < L) aw[threadIdx.x] = expf(raw[threadIdx.x] - m) / ss;
    __syncthreads();
    int j = blockIdx.x * 128 + threadIdx.x;
    float acc = 0.0f;
    #pragma unroll 8
    for (int l = 0; l < L; l++) acc += aw[l] * g_encouts[l * H + j];
    g_applied[j] = acc;
    if (blockIdx.x == 0 && threadIdx.x < L) attns_out[t * L + threadIdx.x] = aw[threadIdx.x];
}

// ---------------- decoder: combine projection + relu ----------------
__global__ void k_comb(const float* __restrict__ dec_emb, const float* __restrict__ W_comb,
                       const float* __restrict__ b_comb) {
    int j = blockIdx.x * 8 + (threadIdx.x >> 5);   // 128 blocks
    const float* e = dec_emb + (long long)g_tok * H;
    const float* Wr = W_comb + j * 2 * H;
    float s = warp_dot(Wr, e, H);
    float s2 = warp_dot(Wr + H, g_applied, H);
    if ((threadIdx.x & 31) == 0) g_xvec[j] = fmaxf(s + s2 + b_comb[j], 0.0f);
}

// ---------------- decoder: GRU step (6 interleaved row-dots) --------------
__global__ void k_dgru(const float* __restrict__ W_ih, const float* __restrict__ W_hh,
                       const float* __restrict__ b_ih, const float* __restrict__ b_hh) {
    int hi = blockIdx.x * 8 + (threadIdx.x >> 5);   // 128 blocks
    int lane = threadIdx.x & 31;
    const float4* x4 = (const float4*)g_xvec;
    const float4* h4 = (const float4*)g_dech;
    const float4* i0 = (const float4*)(W_ih + (long long)hi * H);
    const float4* i1 = (const float4*)(W_ih + (long long)(H + hi) * H);
    const float4* i2 = (const float4*)(W_ih + (long long)(2 * H + hi) * H);
    const float4* q0 = (const float4*)(W_hh + (long long)hi * H);
    const float4* q1 = (const float4*)(W_hh + (long long)(H + hi) * H);
    const float4* q2 = (const float4*)(W_hh + (long long)(2 * H + hi) * H);
    float gi0 = 0.f, gi1 = 0.f, gi2 = 0.f, gh0 = 0.f, gh1 = 0.f, gh2 = 0.f;
    #pragma unroll
    for (int i = 0; i < 8; i++) {
        int j = i * 32 + lane;
        float4 xv = x4[j], hv = h4[j];
        float4 wa = i0[j], wb = i1[j], wc = i2[j];
        float4 wd = q0[j], we = q1[j], wf = q2[j];
        gi0 += wa.x * xv.x + wa.y * xv.y + wa.z * xv.z + wa.w * xv.w;
        gi1 += wb.x * xv.x + wb.y * xv.y + wb.z * xv.z + wb.w * xv.w;
        gi2 += wc.x * xv.x + wc.y * xv.y + wc.z * xv.z + wc.w * xv.w;
        gh0 += wd.x * hv.x + wd.y * hv.y + wd.z * hv.z + wd.w * hv.w;
        gh1 += we.x * hv.x + we.y * hv.y + we.z * hv.z + we.w * hv.w;
        gh2 += wf.x * hv.x + wf.y * hv.y + wf.z * hv.z + wf.w * hv.w;
    }
    gi0 = wred(gi0); gi1 = wred(gi1); gi2 = wred(gi2);
    gh0 = wred(gh0); gh1 = wred(gh1); gh2 = wred(gh2);
    if (lane == 0) {
        float r = sigmoidf_(gi0 + b_ih[hi] + gh0 + b_hh[hi]);
        float z = sigmoidf_(gi1 + b_ih[H + hi] + gh1 + b_hh[H + hi]);
        float n = tanhf(gi2 + b_ih[2 * H + hi] + r * (gh2 + b_hh[2 * H + hi]));
        g_h2[hi] = (1.0f - z) * n + z * g_dech[hi];
    }
}

// ---------------- decoder: bf16 output projection + per-block stats -------
__global__ void k_out(const float* __restrict__ b_out) {
    __shared__ __align__(16) float h4s[H];
    __shared__ float s_exp[16], s_raw[16], s_abs[16];
    int tid = threadIdx.x, lane = tid & 31, w = tid >> 5;
    ((float4*)h4s)[tid] = ((const float4*)g_h2)[tid];   // 256 x float4 = 1024
    __syncthreads();
    const float4* hs4 = (const float4*)h4s;
    #pragma unroll
    for (int k = 0; k < 2; k++) {
        int v = blockIdx.x * 16 + w * 2 + k;
        const uint4* Wr = (const uint4*)(g_Wbf + (size_t)v * H);   // 128 uint4/row
        float acc = 0.f, aa = 0.f;
        #pragma unroll
        for (int jj = 0; jj < 4; jj++) {
            int j = jj * 32 + lane;
            uint4 u = Wr[j];
            float4 ha = hs4[2 * j], hb = hs4[2 * j + 1];
            float2 p0 = __bfloat1622float2(*(const __nv_bfloat162*)&u.x);
            float2 p1 = __bfloat1622float2(*(const __nv_bfloat162*)&u.y);
            float2 p2 = __bfloat1622float2(*(const __nv_bfloat162*)&u.z);
            float2 p3 = __bfloat1622float2(*(const __nv_bfloat162*)&u.w);
            acc += p0.x * ha.x + p0.y * ha.y + p1.x * ha.z + p1.y * ha.w
                 + p2.x * hb.x + p2.y * hb.y + p3.x * hb.z + p3.y * hb.w;
            aa += fabsf(p0.x * ha.x) + fabsf(p0.y * ha.y) + fabsf(p1.x * ha.z) + fabsf(p1.y * ha.w)
                + fabsf(p2.x * hb.x) + fabsf(p2.y * hb.y) + fabsf(p3.x * hb.z) + fabsf(p3.y * hb.w);
        }
        acc = wred(acc); aa = wred(aa);
        if (lane == 0) {
            float raw = acc + b_out[v];
            g_raw[v] = raw;
            s_exp[w * 2 + k] = expf(raw);
            s_raw[w * 2 + k] = raw;
            s_abs[w * 2 + k] = aa;
        }
    }
    __syncthreads();
    if (tid == 0) {
        float se = 0.f, rm = -3.0e38f, ab = 0.f;
        #pragma unroll
        for (int i = 0; i < 16; i++) {
            se += s_exp[i]; rm = fmaxf(rm, s_raw[i]); ab = fmaxf(ab, s_abs[i]);
        }
        g_blocksum2[blockIdx.x] = se;
        g_blockcmax[blockIdx.x] = rm;
        g_blockabs[blockIdx.x] = ab;
    }
}

// ---------------- decoder: reduce + exact fp32 argmax rescore + update ----
__global__ void k_reduce(const float* __restrict__ W_out, const float* __restrict__ b_out,
                         float* __restrict__ toks_out, int t) {
    __shared__ float ssum[1024];
    __shared__ float sam[1024];
    __shared__ float scm[1024];
    __shared__ int s_cand[64];
    __shared__ unsigned long long s_cpk[64];
    __shared__ int s_cnt;
    int tid = threadIdx.x;
    int done_prev = g_done;            // all threads read before thread 0 rewrites
    float s = 0.f, am = 0.f, cm = -3.0e38f;
    for (int i = tid; i < NB2; i += 1024) {
        s += g_blocksum2[i];
        am = fmaxf(am, g_blockabs[i]);
        cm = fmaxf(cm, g_blockcmax[i]);
    }
    ssum[tid] = s; sam[tid] = am; scm[tid] = cm;
    if (tid == 0) s_cnt = 0;
    __syncthreads();
    for (int o = 512; o; o >>= 1) {
        if (tid < o) {
            ssum[tid] += ssum[tid + o];
            sam[tid] = fmaxf(sam[tid], sam[tid + o]);
            scm[tid] = fmaxf(scm[tid], scm[tid + o]);
        }
        __syncthreads();
    }
    // tau bounds |true_fp32_logit - bf16_logit|: bf16 rounding <= 2^-9 per weight
    float tau = sam[0] * (1.5f / 512.0f) + 1e-6f;
    float thr = scm[0] - 2.0f * tau;
    for (int i = tid; i < V; i += 1024) {
        if (g_raw[i] >= thr) {
            int p = atomicAdd(&s_cnt, 1);
            if (p < 64) s_cand[p] = i;
        }
    }
    __syncthreads();
    int nc = min(s_cnt, 64);
    int w = tid >> 5;
    for (int c = w; c < nc; c += 32) {
        int v = s_cand[c];
        float d = warp_dot(W_out + (size_t)v * H, g_h2, H);
        if ((tid & 31) == 0)
            s_cpk[c] = (((unsigned long long)f2mono(d + b_out[v])) << 32)
                     | (unsigned)(0xFFFFFFFFu - (unsigned)v);
    }
    __syncthreads();
    if (tid == 0) {
        unsigned long long best = 0ull;
        for (int c = 0; c < nc; c++) if (s_cpk[c] > best) best = s_cpk[c];
        int nxt = (int)(0xFFFFFFFFu - (unsigned)(best & 0xFFFFFFFFull));
        g_logZ = logf(ssum[0]);
        int tok_out = done_prev ? g_tok : nxt;
        toks_out[t] = (float)tok_out;
        if (!done_prev) g_tok = nxt;
        g_done = done_prev | (nxt == EOS_TOK);
    }
    if (!done_prev) g_dech[tid] = g_h2[tid];
}

// ---------------- decoder: write log-softmax row --------------------------
__global__ void k_write(float* __restrict__ logits_out, int t) {
    int v = blockIdx.x * 256 + threadIdx.x;   // 125 blocks
    logits_out[(long long)t * V + v] = g_raw[v] - g_logZ;
}

// ---------------- host launch ----------------
extern "C" void kernel_launch(void* const* d_in, const int* in_sizes, int n_in,
                              void* d_out, int out_size) {
    const int* qids      = (const int*)d_in[0];
    const int* cids      = (const int*)d_in[1];
    const float* enc_emb = (const float*)d_in[2];
    const float* enc_Wih = (const float*)d_in[3];
    const float* enc_Whh = (const float*)d_in[4];
    const float* enc_bih = (const float*)d_in[5];
    const float* enc_bhh = (const float*)d_in[6];
    const float* dec_emb = (const float*)d_in[7];
    const float* W_attn  = (const float*)d_in[8];
    const float* b_attn  = (const float*)d_in[9];
    const float* W_comb  = (const float*)d_in[10];
    const float* b_comb  = (const float*)d_in[11];
    const float* dW_ih   = (const float*)d_in[12];
    const float* dW_hh   = (const float*)d_in[13];
    const float* db_ih   = (const float*)d_in[14];
    const float* db_hh   = (const float*)d_in[15];
    const float* W_out   = (const float*)d_in[16];
    const float* b_out   = (const float*)d_in[17];

    float* out        = (float*)d_out;
    float* logits_out = out;
    float* attns_out  = out + (long long)L * V;
    float* toks_out   = attns_out + L * L;

    k_init<<<1, 1024>>>();
    k_prep<<<(V * H) / (8 * 256), 256>>>(W_out);   // 16000 blocks
    k_gather<<<E * L, 256>>>(qids, cids, enc_emb);
    k_gi<<<E * 192, 256>>>(enc_Wih, enc_bih);
    for (int t = 0; t < L; t++)
        k_enc_step<<<E * 128, 256>>>(enc_Whh, enc_bhh, t);
    k_combine<<<L * H / 256, 256>>>();

    for (int t = 0; t < L; t++) {
        k_attn<<<8, 256>>>(dec_emb, W_attn, b_attn);
        k_apply<<<8, 128>>>(attns_out, t);
        k_comb<<<128, 256>>>(dec_emb, W_comb, b_comb);
        k_dgru<<<128, 256>>>(dW_ih, dW_hh, db_ih, db_hh);
        k_out<<<NB2, 256>>>(b_out);
        k_reduce<<<1, 1024>>>(W_out, b_out, toks_out, t);
        k_write<<<V / 256, 256>>>(logits_out, t);
    }
}

// round 8
// speedup vs baseline: 1.1626x; 1.1626x over previous
#include <cuda_runtime.h>
#include <cuda_bf16.h>

#define H 1024
#define V 32000
#define L 64
#define E 3
#define EOS_TOK 1
#define NT 512                     // threads per block in k_all
#define NWPB 16                    // warps per block in k_all

// ---------------- device scratch (no allocations allowed) ----------------
__device__ __align__(16) float g_X[E * L * H];        // gathered encoder inputs
__device__ __align__(16) float g_gi[E * L * 3 * H];   // precomputed W_ih @ x + b_ih
__device__ float g_outs[E * L * H];                   // per-encoder outputs (= hidden chain)
__device__ __align__(16) float g_zero[H];             // stays zero (module init)
__device__ float g_encouts[L * H];                    // combined encoder outputs
__device__ __align__(16) float g_M[H * L];            // Wc_applied @ encouts^T
__device__ __align__(16) float g_dech[H];             // decoder hidden
__device__ __align__(16) float g_h2[H];               // candidate next hidden
__device__ float g_awraw[L];                          // raw attention logits
__device__ __align__(16) float g_xvec[H];             // decoder GRU input
__device__ float g_raw[V];                            // raw output logits (bf16-weight path)
__device__ float g_blocksum2[256];                    // per-block sum of exp
__device__ float g_blockcmax[256];                    // per-block max raw
__device__ float g_blockabs[256];                     // per-block max sum|w||h|
__device__ __align__(16) __nv_bfloat16 g_Wbf[(size_t)V * H];  // bf16 copy of W_out
__device__ int g_tok;
__device__ int g_done;
__device__ float g_logZ;
__device__ unsigned g_bar_cnt;
__device__ unsigned g_bar_gen;

// ---------------- helpers ----------------
__device__ __forceinline__ float sigmoidf_(float x) { return 1.0f / (1.0f + expf(-x)); }

__device__ __forceinline__ float wred(float s) {
    #pragma unroll
    for (int o = 16; o; o >>= 1) s += __shfl_down_sync(0xffffffffu, s, o);
    return s;
}

// per-lane partial of dot over H=1024; caller must wred
__device__ __forceinline__ float dotH_lane(const float* __restrict__ row,
                                           const float* __restrict__ vec, int lane) {
    const float4* r4 = (const float4*)row;
    const float4* v4 = (const float4*)vec;
    float s = 0.f;
    #pragma unroll
    for (int i = 0; i < 8; i++) {
        float4 a = r4[i * 32 + lane], b = v4[i * 32 + lane];
        s += a.x * b.x + a.y * b.y + a.z * b.z + a.w * b.w;
    }
    return s;
}

__device__ __forceinline__ unsigned f2mono(float x) {
    unsigned u = __float_as_uint(x);
    return (u & 0x80000000u) ? ~u : (u | 0x80000000u);
}

// grid-wide barrier: generation counter, all blocks co-resident by construction
__device__ __forceinline__ void gsync(int nblk, unsigned& gen) {
    __syncthreads();
    if (threadIdx.x == 0) {
        __threadfence();
        unsigned old = atomicAdd(&g_bar_cnt, 1u);
        if (old == (gen + 1u) * (unsigned)nblk - 1u) {
            __threadfence();
            atomicExch(&g_bar_gen, gen + 1u);
        } else {
            volatile unsigned* p = &g_bar_gen;
            while (*p < gen + 1u) {}
        }
        __threadfence();
    }
    __syncthreads();
    gen++;
}

// ---------------- init ----------------
__global__ void k_init() {
    int i = threadIdx.x;
    if (i < H) g_dech[i] = 0.0f;
    if (i == 0) { g_tok = 0; g_done = 0; g_bar_cnt = 0u; g_bar_gen = 0u; }
}

// ---------------- convert W_out to bf16 (once per launch) ----------------
__global__ void k_prep(const float* __restrict__ W) {
    size_t i8 = ((size_t)blockIdx.x * 256 + threadIdx.x) * 8;
    const float4* W4 = (const float4*)W;
    float4 a = W4[i8 >> 2], b = W4[(i8 >> 2) + 1];
    __nv_bfloat16 tmp[8];
    tmp[0] = __float2bfloat16_rn(a.x); tmp[1] = __float2bfloat16_rn(a.y);
    tmp[2] = __float2bfloat16_rn(a.z); tmp[3] = __float2bfloat16_rn(a.w);
    tmp[4] = __float2bfloat16_rn(b.x); tmp[5] = __float2bfloat16_rn(b.y);
    tmp[6] = __float2bfloat16_rn(b.z); tmp[7] = __float2bfloat16_rn(b.w);
    *(uint4*)(g_Wbf + i8) = *(uint4*)tmp;
}

// ---------------- encoder: gather embeddings ----------------
__global__ void k_gather(const int* __restrict__ qids, const int* __restrict__ cids,
                         const float* __restrict__ emb) {
    int e = blockIdx.x / L, t = blockIdx.x % L;
    int id = (e == 0) ? qids[t] : cids[(e - 1) * L + t];
    const float* src = emb + ((long long)e * V + id) * H;
    float* dst = g_X + (e * L + t) * H;
    for (int j = threadIdx.x; j < H; j += blockDim.x) dst[j] = src[j];
}

// ---------------- gi = W_ih @ X + b_ih (64x64 tile, 4x4 register blocking) ----
__global__ __launch_bounds__(256) void k_gi2(const float* __restrict__ W,
                                             const float* __restrict__ b) {
    __shared__ __align__(16) float Ws[64][68];
    __shared__ __align__(16) float Xs[64][68];
    int e = blockIdx.x / 48, rt = blockIdx.x % 48;
    int row0 = rt * 64;
    const float* Wb = W + ((long long)e * 3072 + row0) * H;
    const float* Xb = g_X + e * L * H;
    int tx = threadIdx.x & 15, ty = threadIdx.x >> 4;
    float acc[4][4] = {};
    for (int kt = 0; kt < 16; kt++) {
        for (int i = threadIdx.x; i < 1024; i += 256) {
            int r = i >> 4, c4 = i & 15;
            *(float4*)&Ws[r][c4 * 4] = *(const float4*)(Wb + (long long)r * H + kt * 64 + c4 * 4);
            *(float4*)&Xs[r][c4 * 4] = *(const float4*)(Xb + r * H + kt * 64 + c4 * 4);
        }
        __syncthreads();
        #pragma unroll
        for (int k4 = 0; k4 < 16; k4++) {
            float4 wv[4], xv[4];
            #pragma unroll
            for (int i = 0; i < 4; i++) wv[i] = *(const float4*)&Ws[ty * 4 + i][k4 * 4];
            #pragma unroll
            for (int i = 0; i < 4; i++) xv[i] = *(const float4*)&Xs[tx * 4 + i][k4 * 4];
            #pragma unroll
            for (int i = 0; i < 4; i++)
                #pragma unroll
                for (int j = 0; j < 4; j++)
                    acc[i][j] += wv[i].x * xv[j].x + wv[i].y * xv[j].y
                               + wv[i].z * xv[j].z + wv[i].w * xv[j].w;
        }
        __syncthreads();
    }
    #pragma unroll
    for (int i = 0; i < 4; i++) {
        int row = row0 + ty * 4 + i;
        float bias = b[e * 3072 + row];
        #pragma unroll
        for (int j = 0; j < 4; j++) {
            int tokn = tx * 4 + j;
            g_gi[(e * L + tokn) * 3072 + row] = acc[i][j] + bias;
        }
    }
}

// ---------------- persistent kernel: encoder recurrence + full decode -----
__global__ __launch_bounds__(NT, 1) void k_all(
    const float* __restrict__ enc_Whh, const float* __restrict__ enc_bhh,
    const float* __restrict__ dec_emb, const float* __restrict__ W_attn,
    const float* __restrict__ b_attn, const float* __restrict__ W_comb,
    const float* __restrict__ b_comb, const float* __restrict__ dW_ih,
    const float* __restrict__ dW_hh, const float* __restrict__ db_ih,
    const float* __restrict__ db_hh, const float* __restrict__ W_out,
    const float* __restrict__ b_out, float* __restrict__ logits_out,
    float* __restrict__ attns_out, float* __restrict__ toks_out, int nblk) {

    __shared__ __align__(16) float sbuf[H];         // enc row / scratch
    __shared__ float s_raw[L], s_aw[L];
    __shared__ float s_r1[NT], s_r2[NT], s_r3[NT];
    __shared__ int s_cand[64];
    __shared__ unsigned long long s_cpk[64];
    __shared__ int s_cnt;

    const int tid = threadIdx.x, lane = tid & 31, wid = tid >> 5;
    const int gw = blockIdx.x * NWPB + wid;
    const int nwarp = nblk * NWPB;
    unsigned gen = 0;

    // ================= encoder recurrence =================
    for (int t = 0; t < L; t++) {
        for (int r = gw; r < 3 * H; r += nwarp) {
            int e = r >> 10, hi = r & (H - 1);
            const float* hin = (t == 0) ? g_zero : (g_outs + (e * L + t - 1) * H);
            const float* W = enc_Whh + (long long)e * 3 * H * H;
            const float4* h4 = (const float4*)hin;
            const float4* r0 = (const float4*)(W + (long long)hi * H);
            const float4* r1 = (const float4*)(W + (long long)(H + hi) * H);
            const float4* r2 = (const float4*)(W + (long long)(2 * H + hi) * H);
            float a0 = 0.f, a1 = 0.f, a2 = 0.f;
            #pragma unroll
            for (int i = 0; i < 8; i++) {
                int j = i * 32 + lane;
                float4 hv = h4[j];
                float4 w0 = r0[j], w1 = r1[j], w2 = r2[j];
                a0 += w0.x * hv.x + w0.y * hv.y + w0.z * hv.z + w0.w * hv.w;
                a1 += w1.x * hv.x + w1.y * hv.y + w1.z * hv.z + w1.w * hv.w;
                a2 += w2.x * hv.x + w2.y * hv.y + w2.z * hv.z + w2.w * hv.w;
            }
            a0 = wred(a0); a1 = wred(a1); a2 = wred(a2);
            if (lane == 0) {
                const float* gi = g_gi + (e * L + t) * 3 * H;
                const float* bh = enc_bhh + e * 3 * H;
                float rr = sigmoidf_(gi[hi] + a0 + bh[hi]);
                float z = sigmoidf_(gi[H + hi] + a1 + bh[H + hi]);
                float n = tanhf(gi[2 * H + hi] + rr * (a2 + bh[2 * H + hi]));
                g_outs[(e * L + t) * H + hi] = (1.0f - z) * n + z * hin[hi];
            }
        }
        gsync(nblk, gen);
    }

    // ================= combine encoder outputs =================
    for (int i = blockIdx.x * NT + tid; i < L * H; i += nblk * NT)
        g_encouts[i] = g_outs[i] + 0.5f * (g_outs[L * H + i] + g_outs[2 * L * H + i]);
    gsync(nblk, gen);

    // ================= M = Wc_applied @ encouts^T (one-time) =================
    if (blockIdx.x < 64) {
        int j = blockIdx.x * NWPB + wid;                 // 0..1023
        float4 wreg[8];
        const float4* Wr = (const float4*)(W_comb + (long long)j * 2 * H + H);
        #pragma unroll
        for (int i = 0; i < 8; i++) wreg[i] = Wr[i * 32 + lane];
        for (int l = 0; l < L; l++) {
            for (int i = tid; i < 256; i += NT)
                ((float4*)sbuf)[i] = ((const float4*)(g_encouts + l * H))[i];
            __syncthreads();
            float s = 0.f;
            #pragma unroll
            for (int i = 0; i < 8; i++) {
                float4 ev = ((const float4*)sbuf)[i * 32 + lane];
                s += wreg[i].x * ev.x + wreg[i].y * ev.y + wreg[i].z * ev.z + wreg[i].w * ev.w;
            }
            s = wred(s);
            if (lane == 0) g_M[j * L + l] = s;
            __syncthreads();
        }
    }
    gsync(nblk, gen);

    // ================= greedy attention decode =================
    for (int t = 0; t < L; t++) {
        // ---- phase A: attn raw logits + write previous logits row ----
        int tok = g_tok;
        const float* evec = dec_emb + (long long)tok * H;
        if (t > 0) {
            float lz = g_logZ;
            for (int i = blockIdx.x * NT + tid; i < V; i += nblk * NT)
                logits_out[(long long)(t - 1) * V + i] = g_raw[i] - lz;
        }
        if (gw < L) {
            float s = dotH_lane(W_attn + gw * 2 * H, evec, lane)
                    + dotH_lane(W_attn + gw * 2 * H + H, g_dech, lane);
            s = wred(s);
            if (lane == 0) g_awraw[gw] = s + b_attn[gw];
        }
        gsync(nblk, gen);

        // ---- phase B: softmax(aw) + xvec = relu(Wc_e . e + M . aw + b) ----
        if (tid < L) s_raw[tid] = g_awraw[tid];
        __syncthreads();
        if (tid < L) {
            float m = -3.0e38f;
            for (int l = 0; l < L; l++) m = fmaxf(m, s_raw[l]);
            float ss = 0.f;
            for (int l = 0; l < L; l++) ss += expf(s_raw[l] - m);
            s_aw[tid] = expf(s_raw[tid] - m) / ss;
        }
        __syncthreads();
        if (blockIdx.x == 0 && tid < L) attns_out[t * L + tid] = s_aw[tid];
        if (gw < H) {
            int j = gw;
            float s = dotH_lane(W_comb + (long long)j * 2 * H, evec, lane);
            float2 m2 = ((const float2*)(g_M + j * L))[lane];
            s += m2.x * s_aw[2 * lane] + m2.y * s_aw[2 * lane + 1];
            s = wred(s);
            if (lane == 0) g_xvec[j] = fmaxf(s + b_comb[j], 0.0f);
        }
        gsync(nblk, gen);

        // ---- phase C: decoder GRU ----
        if (gw < H) {
            int hi = gw;
            const float4* x4 = (const float4*)g_xvec;
            const float4* h4 = (const float4*)g_dech;
            const float4* i0 = (const float4*)(dW_ih + (long long)hi * H);
            const float4* i1 = (const float4*)(dW_ih + (long long)(H + hi) * H);
            const float4* i2 = (const float4*)(dW_ih + (long long)(2 * H + hi) * H);
            const float4* q0 = (const float4*)(dW_hh + (long long)hi * H);
            const float4* q1 = (const float4*)(dW_hh + (long long)(H + hi) * H);
            const float4* q2 = (const float4*)(dW_hh + (long long)(2 * H + hi) * H);
            float gi0 = 0.f, gi1 = 0.f, gi2 = 0.f, gh0 = 0.f, gh1 = 0.f, gh2 = 0.f;
            #pragma unroll
            for (int i = 0; i < 8; i++) {
                int j = i * 32 + lane;
                float4 xv = x4[j], hv = h4[j];
                float4 wa = i0[j], wb = i1[j], wc = i2[j];
                float4 wd = q0[j], we = q1[j], wf = q2[j];
                gi0 += wa.x * xv.x + wa.y * xv.y + wa.z * xv.z + wa.w * xv.w;
                gi1 += wb.x * xv.x + wb.y * xv.y + wb.z * xv.z + wb.w * xv.w;
                gi2 += wc.x * xv.x + wc.y * xv.y + wc.z * xv.z + wc.w * xv.w;
                gh0 += wd.x * hv.x + wd.y * hv.y + wd.z * hv.z + wd.w * hv.w;
                gh1 += we.x * hv.x + we.y * hv.y + we.z * hv.z + we.w * hv.w;
                gh2 += wf.x * hv.x + wf.y * hv.y + wf.z * hv.z + wf.w * hv.w;
            }
            gi0 = wred(gi0); gi1 = wred(gi1); gi2 = wred(gi2);
            gh0 = wred(gh0); gh1 = wred(gh1); gh2 = wred(gh2);
            if (lane == 0) {
                float rr = sigmoidf_(gi0 + db_ih[hi] + gh0 + db_hh[hi]);
                float z = sigmoidf_(gi1 + db_ih[H + hi] + gh1 + db_hh[H + hi]);
                float n = tanhf(gi2 + db_ih[2 * H + hi] + rr * (gh2 + db_hh[2 * H + hi]));
                g_h2[hi] = (1.0f - z) * n + z * g_dech[hi];
            }
        }
        gsync(nblk, gen);

        // ---- phase D: bf16 output projection + per-block stats ----
        {
            float4 hr[8];
            const float4* h4 = (const float4*)g_h2;
            #pragma unroll
            for (int jj = 0; jj < 4; jj++) {
                hr[2 * jj] = h4[(jj * 32 + lane) * 2];
                hr[2 * jj + 1] = h4[(jj * 32 + lane) * 2 + 1];
            }
            float se = 0.f, rm = -3.0e38f, ab = 0.f;
            for (int v = gw; v < V; v += nwarp) {
                const uint4* Wr = (const uint4*)(g_Wbf + (size_t)v * H);
                float acc = 0.f, aa = 0.f;
                #pragma unroll
                for (int jj = 0; jj < 4; jj++) {
                    uint4 u = Wr[jj * 32 + lane];
                    float4 ha = hr[2 * jj], hb = hr[2 * jj + 1];
                    float2 p0 = __bfloat1622float2(*(const __nv_bfloat162*)&u.x);
                    float2 p1 = __bfloat1622float2(*(const __nv_bfloat162*)&u.y);
                    float2 p2 = __bfloat1622float2(*(const __nv_bfloat162*)&u.z);
                    float2 p3 = __bfloat1622float2(*(const __nv_bfloat162*)&u.w);
                    acc += p0.x * ha.x + p0.y * ha.y + p1.x * ha.z + p1.y * ha.w
                         + p2.x * hb.x + p2.y * hb.y + p3.x * hb.z + p3.y * hb.w;
                    aa += fabsf(p0.x * ha.x) + fabsf(p0.y * ha.y) + fabsf(p1.x * ha.z)
                        + fabsf(p1.y * ha.w) + fabsf(p2.x * hb.x) + fabsf(p2.y * hb.y)
                        + fabsf(p3.x * hb.z) + fabsf(p3.y * hb.w);
                }
                acc = wred(acc); aa = wred(aa);
                if (lane == 0) {
                    float raw = acc + b_out[v];
                    g_raw[v] = raw;
                    se += expf(raw);
                    rm = fmaxf(rm, raw);
                    ab = fmaxf(ab, aa);
                }
            }
            if (lane == 0) { s_r1[wid] = se; s_r2[wid] = rm; s_r3[wid] = ab; }
            __syncthreads();
            if (tid == 0) {
                float s = 0.f, m = -3.0e38f, a = 0.f;
                #pragma unroll
                for (int i = 0; i < NWPB; i++) {
                    s += s_r1[i]; m = fmaxf(m, s_r2[i]); a = fmaxf(a, s_r3[i]);
                }
                g_blocksum2[blockIdx.x] = s;
                g_blockcmax[blockIdx.x] = m;
                g_blockabs[blockIdx.x] = a;
            }
        }
        gsync(nblk, gen);

        // ---- phase E: block 0 reduces, rescores candidates in fp32, updates ----
        if (blockIdx.x == 0) {
            int done_prev = g_done;
            float s = 0.f, am = 0.f, cm = -3.0e38f;
            if (tid < nblk) { s = g_blocksum2[tid]; am = g_blockabs[tid]; cm = g_blockcmax[tid]; }
            s_r1[tid] = s; s_r2[tid] = cm; s_r3[tid] = am;
            if (tid == 0) s_cnt = 0;
            __syncthreads();
            for (int o = NT / 2; o; o >>= 1) {
                if (tid < o) {
                    s_r1[tid] += s_r1[tid + o];
                    s_r2[tid] = fmaxf(s_r2[tid], s_r2[tid + o]);
                    s_r3[tid] = fmaxf(s_r3[tid], s_r3[tid + o]);
                }
                __syncthreads();
            }
            float tau = s_r3[0] * (1.5f / 512.0f) + 1e-6f;
            float thr = s_r2[0] - 2.0f * tau;
            for (int i = tid; i < V; i += NT) {
                if (g_raw[i] >= thr) {
                    int p = atomicAdd(&s_cnt, 1);
                    if (p < 64) s_cand[p] = i;
                }
            }
            __syncthreads();
            int nc = min(s_cnt, 64);
            for (int c = wid; c < nc; c += NWPB) {
                int v = s_cand[c];
                float d = dotH_lane(W_out + (size_t)v * H, g_h2, lane);
                d = wred(d);
                if (lane == 0)
                    s_cpk[c] = (((unsigned long long)f2mono(d + b_out[v])) << 32)
                             | (unsigned)(0xFFFFFFFFu - (unsigned)v);
            }
            __syncthreads();
            if (tid == 0) {
                unsigned long long best = 0ull;
                for (int c = 0; c < nc; c++) if (s_cpk[c] > best) best = s_cpk[c];
                int nxt = (int)(0xFFFFFFFFu - (unsigned)(best & 0xFFFFFFFFull));
                g_logZ = logf(s_r1[0]);
                int tok_out = done_prev ? tok : nxt;
                toks_out[t] = (float)tok_out;
                if (!done_prev) g_tok = nxt;
                g_done = done_prev | (nxt == EOS_TOK);
            }
            __syncthreads();
            if (!done_prev)
                for (int i = tid; i < H; i += NT) g_dech[i] = g_h2[i];
        }
        gsync(nblk, gen);
    }

    // final logits row
    {
        float lz = g_logZ;
        for (int i = blockIdx.x * NT + tid; i < V; i += nblk * NT)
            logits_out[(long long)(L - 1) * V + i] = g_raw[i] - lz;
    }
}

// ---------------- host launch ----------------
extern "C" void kernel_launch(void* const* d_in, const int* in_sizes, int n_in,
                              void* d_out, int out_size) {
    const int* qids      = (const int*)d_in[0];
    const int* cids      = (const int*)d_in[1];
    const float* enc_emb = (const float*)d_in[2];
    const float* enc_Wih = (const float*)d_in[3];
    const float* enc_Whh = (const float*)d_in[4];
    const float* enc_bih = (const float*)d_in[5];
    const float* enc_bhh = (const float*)d_in[6];
    const float* dec_emb = (const float*)d_in[7];
    const float* W_attn  = (const float*)d_in[8];
    const float* b_attn  = (const float*)d_in[9];
    const float* W_comb  = (const float*)d_in[10];
    const float* b_comb  = (const float*)d_in[11];
    const float* dW_ih   = (const float*)d_in[12];
    const float* dW_hh   = (const float*)d_in[13];
    const float* db_ih   = (const float*)d_in[14];
    const float* db_hh   = (const float*)d_in[15];
    const float* W_out   = (const float*)d_in[16];
    const float* b_out   = (const float*)d_in[17];

    float* out        = (float*)d_out;
    float* logits_out = out;
    float* attns_out  = out + (long long)L * V;
    float* toks_out   = attns_out + L * L;

    int dev = 0, sms = 148;
    cudaGetDevice(&dev);
    cudaDeviceGetAttribute(&sms, cudaDevAttrMultiProcessorCount, dev);
    int nblk = sms;
    if (nblk > 256) nblk = 256;
    if (nblk < 64) nblk = 64;   // M phase needs 64 blocks; SM count is >= 64 on GB300

    k_init<<<1, 1024>>>();
    k_prep<<<(V * H) / (8 * 256), 256>>>(W_out);
    k_gather<<<E * L, 256>>>(qids, cids, enc_emb);
    k_gi2<<<E * 48, 256>>>(enc_Wih, enc_bih);
    k_all<<<nblk, NT>>>(enc_Whh, enc_bhh, dec_emb, W_attn, b_attn, W_comb, b_comb,
                        dW_ih, dW_hh, db_ih, db_hh, W_out, b_out,
                        logits_out, attns_out, toks_out, nblk);
}

// round 9
// speedup vs baseline: 1.3376x; 1.1505x over previous
#include <cuda_runtime.h>
#include <cuda_bf16.h>

#define H 1024
#define V 32000
#define L 64
#define E 3
#define EOS_TOK 1
#define NT 512                     // threads per block in k_all
#define NWPB 16                    // warps per block in k_all

// ---------------- device scratch (no allocations allowed) ----------------
__device__ __align__(16) float g_X[E * L * H];        // gathered encoder inputs
__device__ __align__(16) float g_giA[E * L * 3 * H];  // W_ih @ x partial (K first half)
__device__ __align__(16) float g_giB[E * L * 3 * H];  // W_ih @ x partial (K second half)
__device__ float g_outs[E * L * H];                   // per-encoder outputs (= hidden chain)
__device__ __align__(16) float g_zero[H];             // stays zero (module init)
__device__ float g_encouts[L * H];                    // combined encoder outputs
__device__ __align__(16) float g_M[H * L];            // Wc_applied @ encouts^T
__device__ __align__(16) float g_hbuf[2][H];          // decoder hidden double buffer
__device__ float g_gh[3 * H];                         // dW_hh @ h (per step)
__device__ float g_We[H];                             // Wc_e @ e (per step)
__device__ float g_awe[L], g_awh[L];                  // attn logit partials
__device__ __align__(16) float g_xvec[H];             // decoder GRU input
__device__ float g_raw[V];                            // raw output logits (bf16-weight path)
__device__ float g_blocksum2[256];                    // per-block sum of exp
__device__ float g_blockcmax[256];                    // per-block max raw
__device__ float g_blockabs[256];                     // per-block max sum|w||h|
__device__ __align__(16) __nv_bfloat16 g_Wbf[(size_t)V * H];  // bf16 copy of W_out
__device__ unsigned g_bar_cnt;
__device__ unsigned g_bar_gen;

// ---------------- helpers ----------------
__device__ __forceinline__ float sigmoidf_(float x) { return 1.0f / (1.0f + expf(-x)); }

__device__ __forceinline__ float wred(float s) {
    #pragma unroll
    for (int o = 16; o; o >>= 1) s += __shfl_down_sync(0xffffffffu, s, o);
    return s;
}

__device__ __forceinline__ float red16m(float s, unsigned m) {
    #pragma unroll
    for (int o = 8; o; o >>= 1) s += __shfl_down_sync(m, s, o, 16);
    return s;
}

// per-lane partial of dot over H=1024 with 32 lanes; caller must wred
__device__ __forceinline__ float dotH_lane(const float* __restrict__ row,
                                           const float* __restrict__ vec, int lane) {
    const float4* r4 = (const float4*)row;
    const float4* v4 = (const float4*)vec;
    float s = 0.f;
    #pragma unroll
    for (int i = 0; i < 8; i++) {
        float4 a = r4[i * 32 + lane], b = v4[i * 32 + lane];
        s += a.x * b.x + a.y * b.y + a.z * b.z + a.w * b.w;
    }
    return s;
}

// per-lane partial of dot over H=1024 with 16 lanes; caller must red16m
__device__ __forceinline__ float dotH_16(const float* __restrict__ row,
                                         const float* __restrict__ vec, int l16) {
    const float4* r4 = (const float4*)row;
    const float4* v4 = (const float4*)vec;
    float s = 0.f;
    #pragma unroll
    for (int i = 0; i < 16; i++) {
        float4 a = r4[i * 16 + l16], b = v4[i * 16 + l16];
        s += a.x * b.x + a.y * b.y + a.z * b.z + a.w * b.w;
    }
    return s;
}

__device__ __forceinline__ unsigned f2mono(float x) {
    unsigned u = __float_as_uint(x);
    return (u & 0x80000000u) ? ~u : (u | 0x80000000u);
}

// grid-wide barrier: generation counter, all blocks co-resident by construction
__device__ __forceinline__ void gsync(int nblk, unsigned& gen) {
    __syncthreads();
    if (threadIdx.x == 0) {
        __threadfence();
        unsigned old = atomicAdd(&g_bar_cnt, 1u);
        if (old == (gen + 1u) * (unsigned)nblk - 1u) {
            __threadfence();
            atomicExch(&g_bar_gen, gen + 1u);
        } else {
            volatile unsigned* p = &g_bar_gen;
            while (*p < gen + 1u) {}
        }
        __threadfence();
    }
    __syncthreads();
    gen++;
}

// ---------------- init ----------------
__global__ void k_init() {
    int i = threadIdx.x;
    if (i < H) { g_hbuf[0][i] = 0.0f; }
    if (i == 0) { g_bar_cnt = 0u; g_bar_gen = 0u; }
}

// ---------------- convert W_out to bf16 (once per launch) ----------------
__global__ void k_prep(const float* __restrict__ W) {
    size_t i8 = ((size_t)blockIdx.x * 256 + threadIdx.x) * 8;
    const float4* W4 = (const float4*)W;
    float4 a = W4[i8 >> 2], b = W4[(i8 >> 2) + 1];
    __nv_bfloat16 tmp[8];
    tmp[0] = __float2bfloat16_rn(a.x); tmp[1] = __float2bfloat16_rn(a.y);
    tmp[2] = __float2bfloat16_rn(a.z); tmp[3] = __float2bfloat16_rn(a.w);
    tmp[4] = __float2bfloat16_rn(b.x); tmp[5] = __float2bfloat16_rn(b.y);
    tmp[6] = __float2bfloat16_rn(b.z); tmp[7] = __float2bfloat16_rn(b.w);
    *(uint4*)(g_Wbf + i8) = *(uint4*)tmp;
}

// ---------------- encoder: gather embeddings ----------------
__global__ void k_gather(const int* __restrict__ qids, const int* __restrict__ cids,
                         const float* __restrict__ emb) {
    int e = blockIdx.x / L, t = blockIdx.x % L;
    int id = (e == 0) ? qids[t] : cids[(e - 1) * L + t];
    const float* src = emb + ((long long)e * V + id) * H;
    float* dst = g_X + (e * L + t) * H;
    for (int j = threadIdx.x; j < H; j += blockDim.x) dst[j] = src[j];
}

// ---- gi partials = W_ih @ X (64x64 tile, 4x4 reg blocking, split-K 2-way) ----
__global__ __launch_bounds__(256) void k_gi2(const float* __restrict__ W) {
    __shared__ __align__(16) float Ws[64][68];
    __shared__ __align__(16) float Xs[64][68];
    int kh = blockIdx.x / 144;                       // K half: 0 or 1
    int rem = blockIdx.x % 144;
    int e = rem / 48, rt = rem % 48;
    int row0 = rt * 64;
    const float* Wb = W + ((long long)e * 3072 + row0) * H;
    const float* Xb = g_X + e * L * H;
    float* gout = kh ? g_giB : g_giA;
    int tx = threadIdx.x & 15, ty = threadIdx.x >> 4;
    float acc[4][4] = {};
    for (int kt = kh * 8; kt < kh * 8 + 8; kt++) {
        for (int i = threadIdx.x; i < 1024; i += 256) {
            int r = i >> 4, c4 = i & 15;
            *(float4*)&Ws[r][c4 * 4] = *(const float4*)(Wb + (long long)r * H + kt * 64 + c4 * 4);
            *(float4*)&Xs[r][c4 * 4] = *(const float4*)(Xb + r * H + kt * 64 + c4 * 4);
        }
        __syncthreads();
        #pragma unroll
        for (int k4 = 0; k4 < 16; k4++) {
            float4 wv[4], xv[4];
            #pragma unroll
            for (int i = 0; i < 4; i++) wv[i] = *(const float4*)&Ws[ty * 4 + i][k4 * 4];
            #pragma unroll
            for (int i = 0; i < 4; i++) xv[i] = *(const float4*)&Xs[tx * 4 + i][k4 * 4];
            #pragma unroll
            for (int i = 0; i < 4; i++)
                #pragma unroll
                for (int j = 0; j < 4; j++)
                    acc[i][j] += wv[i].x * xv[j].x + wv[i].y * xv[j].y
                               + wv[i].z * xv[j].z + wv[i].w * xv[j].w;
        }
        __syncthreads();
    }
    #pragma unroll
    for (int i = 0; i < 4; i++) {
        int row = row0 + ty * 4 + i;
        #pragma unroll
        for (int j = 0; j < 4; j++) {
            int tokn = tx * 4 + j;
            gout[(e * L + tokn) * 3072 + row] = acc[i][j];
        }
    }
}

// ---------------- persistent kernel: encoder recurrence + full decode -----
__global__ __launch_bounds__(NT, 1) void k_all(
    const float* __restrict__ enc_Whh, const float* __restrict__ enc_bih,
    const float* __restrict__ enc_bhh,
    const float* __restrict__ dec_emb, const float* __restrict__ W_attn,
    const float* __restrict__ b_attn, const float* __restrict__ W_comb,
    const float* __restrict__ b_comb, const float* __restrict__ dW_ih,
    const float* __restrict__ dW_hh, const float* __restrict__ db_ih,
    const float* __restrict__ db_hh, const float* __restrict__ W_out,
    const float* __restrict__ b_out, float* __restrict__ logits_out,
    float* __restrict__ attns_out, float* __restrict__ toks_out, int nblk) {

    __shared__ __align__(16) float sbuf[H];
    __shared__ float s_raw[L], s_aw[L];
    __shared__ float s_r1[NT], s_r2[NT], s_r3[NT];
    __shared__ int s_cand[64];
    __shared__ unsigned long long s_cpk[64];
    __shared__ int s_cnt;

    const int tid = threadIdx.x, lane = tid & 31, wid = tid >> 5;
    const int gw = blockIdx.x * NWPB + wid;
    const int nwarp = nblk * NWPB;
    const int l16 = lane & 15;
    const unsigned hm = (lane < 16) ? 0x0000FFFFu : 0xFFFF0000u;
    unsigned gen = 0;
    int tok = 0, done = 0, cur = 0;    // replicated decode state (deterministic)

    // ================= encoder recurrence (pair of row-triples per warp) ====
    for (int t = 0; t < L; t++) {
        for (int p = gw; p < 1536; p += nwarp) {
            int r = p * 2 + (lane >> 4);              // 0..3071
            int e = r >> 10, hi = r & 1023;
            const float* hin = (t == 0) ? g_zero : (g_outs + (e * L + t - 1) * H);
            const float* W = enc_Whh + (long long)e * 3 * H * H;
            const float4* h4 = (const float4*)hin;
            const float4* r0 = (const float4*)(W + (long long)hi * H);
            const float4* r1 = (const float4*)(W + (long long)(H + hi) * H);
            const float4* r2 = (const float4*)(W + (long long)(2 * H + hi) * H);
            float a0 = 0.f, a1 = 0.f, a2 = 0.f;
            #pragma unroll
            for (int i = 0; i < 16; i++) {
                int j = i * 16 + l16;
                float4 hv = h4[j];
                float4 w0 = r0[j], w1 = r1[j], w2 = r2[j];
                a0 += w0.x * hv.x + w0.y * hv.y + w0.z * hv.z + w0.w * hv.w;
                a1 += w1.x * hv.x + w1.y * hv.y + w1.z * hv.z + w1.w * hv.w;
                a2 += w2.x * hv.x + w2.y * hv.y + w2.z * hv.z + w2.w * hv.w;
            }
            a0 = red16m(a0, 0xffffffffu); a1 = red16m(a1, 0xffffffffu);
            a2 = red16m(a2, 0xffffffffu);
            if (l16 == 0) {
                const float* giA = g_giA + (e * L + t) * 3 * H;
                const float* giB = g_giB + (e * L + t) * 3 * H;
                const float* bi = enc_bih + e * 3 * H;
                const float* bh = enc_bhh + e * 3 * H;
                float rr = sigmoidf_(giA[hi] + giB[hi] + bi[hi] + a0 + bh[hi]);
                float z = sigmoidf_(giA[H + hi] + giB[H + hi] + bi[H + hi] + a1 + bh[H + hi]);
                float n = tanhf(giA[2 * H + hi] + giB[2 * H + hi] + bi[2 * H + hi]
                                + rr * (a2 + bh[2 * H + hi]));
                g_outs[(e * L + t) * H + hi] = (1.0f - z) * n + z * hin[hi];
            }
        }
        gsync(nblk, gen);
    }

    // ================= combine encoder outputs =================
    for (int i = blockIdx.x * NT + tid; i < L * H; i += nblk * NT)
        g_encouts[i] = g_outs[i] + 0.5f * (g_outs[L * H + i] + g_outs[2 * L * H + i]);
    gsync(nblk, gen);

    // ================= M = Wc_applied @ encouts^T (one-time) =================
    if (blockIdx.x < 64) {
        int j = blockIdx.x * NWPB + wid;                 // 0..1023
        float4 wreg[8];
        const float4* Wr = (const float4*)(W_comb + (long long)j * 2 * H + H);
        #pragma unroll
        for (int i = 0; i < 8; i++) wreg[i] = Wr[i * 32 + lane];
        for (int l = 0; l < L; l++) {
            for (int i = tid; i < 256; i += NT)
                ((float4*)sbuf)[i] = ((const float4*)(g_encouts + l * H))[i];
            __syncthreads();
            float s = 0.f;
            #pragma unroll
            for (int i = 0; i < 8; i++) {
                float4 ev = ((const float4*)sbuf)[i * 32 + lane];
                s += wreg[i].x * ev.x + wreg[i].y * ev.y + wreg[i].z * ev.z + wreg[i].w * ev.w;
            }
            s = wred(s);
            if (lane == 0) g_M[j * L + l] = s;
            __syncthreads();
        }
    }
    gsync(nblk, gen);

    // ================= greedy attention decode (4 barriers/step) =============
    for (int t = 0; t < L; t++) {
        // ---- phase A: redundant reduce/argmax of step t-1, token update,
        //      logits row t-1, then gh / We / attn partial dots ----
        if (t > 0) {
            float s = 0.f, am = 0.f, cm = -3.0e38f;
            if (tid < nblk) { s = g_blocksum2[tid]; am = g_blockabs[tid]; cm = g_blockcmax[tid]; }
            s_r1[tid] = s; s_r2[tid] = cm; s_r3[tid] = am;
            __syncthreads();
            for (int o = NT / 2; o; o >>= 1) {
                if (tid < o) {
                    s_r1[tid] += s_r1[tid + o];
                    s_r2[tid] = fmaxf(s_r2[tid], s_r2[tid + o]);
                    s_r3[tid] = fmaxf(s_r3[tid], s_r3[tid + o]);
                }
                __syncthreads();
            }
            float logZ = logf(s_r1[0]);
            float tau = s_r3[0] * (1.5f / 512.0f) + 1e-6f;
            float thr = s_r2[0] - 2.0f * tau;
            if (tid == 0) s_cnt = 0;
            __syncthreads();
            for (int i = tid; i < V; i += NT) {
                if (g_raw[i] >= thr) {
                    int p = atomicAdd(&s_cnt, 1);
                    if (p < 64) s_cand[p] = i;
                }
            }
            __syncthreads();
            int nc = min(s_cnt, 64);
            const float* h2p = g_hbuf[cur ^ 1];          // h2 of step t-1 (pre-flip)
            for (int c = wid; c < nc; c += NWPB) {
                int v = s_cand[c];
                float d = dotH_lane(W_out + (size_t)v * H, h2p, lane);
                d = wred(d);
                if (lane == 0)
                    s_cpk[c] = (((unsigned long long)f2mono(d + b_out[v])) << 32)
                             | (unsigned)(0xFFFFFFFFu - (unsigned)v);
            }
            __syncthreads();
            unsigned long long best = 0ull;
            for (int c = 0; c < nc; c++) if (s_cpk[c] > best) best = s_cpk[c];
            int nxt = (int)(0xFFFFFFFFu - (unsigned)(best & 0xFFFFFFFFull));
            int tokout = done ? tok : nxt;
            if (blockIdx.x == 0 && tid == 0) toks_out[t - 1] = (float)tokout;
            tok = tokout;
            if (!done) cur ^= 1;                         // accept h2_{t-1}
            done = done | (nxt == EOS_TOK);
            for (int i = blockIdx.x * NT + tid; i < V; i += nblk * NT)
                logits_out[(long long)(t - 1) * V + i] = g_raw[i] - logZ;
        }
        const float* evec = dec_emb + (long long)tok * H;
        const float* hcur = g_hbuf[cur];
        // half-warp dot tasks: 3072 gh + 1024 We + 64 attn-e + 64 attn-h = 4224
        for (int q = gw * 2 + (lane >> 4); q < 4224; q += nwarp * 2) {
            if (q < 3072) {
                float s = dotH_16(dW_hh + (long long)q * H, hcur, l16);
                s = red16m(s, hm);
                if (l16 == 0) g_gh[q] = s;
            } else if (q < 4096) {
                int j = q - 3072;
                float s = dotH_16(W_comb + (long long)j * 2 * H, evec, l16);
                s = red16m(s, hm);
                if (l16 == 0) g_We[j] = s;
            } else if (q < 4160) {
                int l = q - 4096;
                float s = dotH_16(W_attn + l * 2 * H, evec, l16);
                s = red16m(s, hm);
                if (l16 == 0) g_awe[l] = s;
            } else {
                int l = q - 4160;
                float s = dotH_16(W_attn + l * 2 * H + H, hcur, l16);
                s = red16m(s, hm);
                if (l16 == 0) g_awh[l] = s;
            }
        }
        gsync(nblk, gen);

        // ---- phase B: softmax(aw) redundant + xvec ----
        if (tid < L) s_raw[tid] = g_awe[tid] + g_awh[tid] + b_attn[tid];
        __syncthreads();
        if (tid < L) {
            float m = -3.0e38f;
            for (int l = 0; l < L; l++) m = fmaxf(m, s_raw[l]);
            float ss = 0.f;
            for (int l = 0; l < L; l++) ss += expf(s_raw[l] - m);
            s_aw[tid] = expf(s_raw[tid] - m) / ss;
        }
        __syncthreads();
        if (blockIdx.x == 0 && tid < L) attns_out[t * L + tid] = s_aw[tid];
        for (int j = gw; j < H; j += nwarp) {
            float2 m2 = ((const float2*)(g_M + j * L))[lane];
            float s = m2.x * s_aw[2 * lane] + m2.y * s_aw[2 * lane + 1];
            s = wred(s);
            if (lane == 0) g_xvec[j] = fmaxf(s + g_We[j] + b_comb[j], 0.0f);
        }
        gsync(nblk, gen);

        // ---- phase C: gi = dW_ih @ xvec + gates -> h2 ----
        for (int hi = gw; hi < H; hi += nwarp) {
            const float4* x4 = (const float4*)g_xvec;
            const float4* i0 = (const float4*)(dW_ih + (long long)hi * H);
            const float4* i1 = (const float4*)(dW_ih + (long long)(H + hi) * H);
            const float4* i2 = (const float4*)(dW_ih + (long long)(2 * H + hi) * H);
            float gi0 = 0.f, gi1 = 0.f, gi2 = 0.f;
            #pragma unroll
            for (int i = 0; i < 8; i++) {
                int j = i * 32 + lane;
                float4 xv = x4[j];
                float4 wa = i0[j], wb = i1[j], wc = i2[j];
                gi0 += wa.x * xv.x + wa.y * xv.y + wa.z * xv.z + wa.w * xv.w;
                gi1 += wb.x * xv.x + wb.y * xv.y + wb.z * xv.z + wb.w * xv.w;
                gi2 += wc.x * xv.x + wc.y * xv.y + wc.z * xv.z + wc.w * xv.w;
            }
            gi0 = wred(gi0); gi1 = wred(gi1); gi2 = wred(gi2);
            if (lane == 0) {
                float hv = g_hbuf[cur][hi];
                float rr = sigmoidf_(gi0 + db_ih[hi] + g_gh[hi] + db_hh[hi]);
                float z = sigmoidf_(gi1 + db_ih[H + hi] + g_gh[H + hi] + db_hh[H + hi]);
                float n = tanhf(gi2 + db_ih[2 * H + hi]
                                + rr * (g_gh[2 * H + hi] + db_hh[2 * H + hi]));
                g_hbuf[cur ^ 1][hi] = (1.0f - z) * n + z * hv;
            }
        }
        gsync(nblk, gen);

        // ---- phase D: bf16 output projection + per-block stats ----
        {
            float4 hr[8];
            const float4* h4 = (const float4*)g_hbuf[cur ^ 1];
            #pragma unroll
            for (int jj = 0; jj < 4; jj++) {
                hr[2 * jj] = h4[(jj * 32 + lane) * 2];
                hr[2 * jj + 1] = h4[(jj * 32 + lane) * 2 + 1];
            }
            float se = 0.f, rm = -3.0e38f, ab = 0.f;
            for (int v = gw; v < V; v += nwarp) {
                const uint4* Wr = (const uint4*)(g_Wbf + (size_t)v * H);
                float acc = 0.f, aa = 0.f;
                #pragma unroll
                for (int jj = 0; jj < 4; jj++) {
                    uint4 u = Wr[jj * 32 + lane];
                    float4 ha = hr[2 * jj], hb = hr[2 * jj + 1];
                    float2 p0 = __bfloat1622float2(*(const __nv_bfloat162*)&u.x);
                    float2 p1 = __bfloat1622float2(*(const __nv_bfloat162*)&u.y);
                    float2 p2 = __bfloat1622float2(*(const __nv_bfloat162*)&u.z);
                    float2 p3 = __bfloat1622float2(*(const __nv_bfloat162*)&u.w);
                    acc += p0.x * ha.x + p0.y * ha.y + p1.x * ha.z + p1.y * ha.w
                         + p2.x * hb.x + p2.y * hb.y + p3.x * hb.z + p3.y * hb.w;
                    aa += fabsf(p0.x * ha.x) + fabsf(p0.y * ha.y) + fabsf(p1.x * ha.z)
                        + fabsf(p1.y * ha.w) + fabsf(p2.x * hb.x) + fabsf(p2.y * hb.y)
                        + fabsf(p3.x * hb.z) + fabsf(p3.y * hb.w);
                }
                acc = wred(acc); aa = wred(aa);
                if (lane == 0) {
                    float raw = acc + b_out[v];
                    g_raw[v] = raw;
                    se += expf(raw);
                    rm = fmaxf(rm, raw);
                    ab = fmaxf(ab, aa);
                }
            }
            if (lane == 0) { s_r1[wid] = se; s_r2[wid] = rm; s_r3[wid] = ab; }
            __syncthreads();
            if (tid == 0) {
                float s = 0.f, m = -3.0e38f, a = 0.f;
                #pragma unroll
                for (int i = 0; i < NWPB; i++) {
                    s += s_r1[i]; m = fmaxf(m, s_r2[i]); a = fmaxf(a, s_r3[i]);
                }
                g_blocksum2[blockIdx.x] = s;
                g_blockcmax[blockIdx.x] = m;
                g_blockabs[blockIdx.x] = a;
            }
        }
        gsync(nblk, gen);
    }

    // ================= epilogue: step L-1 token + final logits row ==========
    {
        float s = 0.f, am = 0.f, cm = -3.0e38f;
        if (tid < nblk) { s = g_blocksum2[tid]; am = g_blockabs[tid]; cm = g_blockcmax[tid]; }
        s_r1[tid] = s; s_r2[tid] = cm; s_r3[tid] = am;
        __syncthreads();
        for (int o = NT / 2; o; o >>= 1) {
            if (tid < o) {
                s_r1[tid] += s_r1[tid + o];
                s_r2[tid] = fmaxf(s_r2[tid], s_r2[tid + o]);
                s_r3[tid] = fmaxf(s_r3[tid], s_r3[tid + o]);
            }
            __syncthreads();
        }
        float logZ = logf(s_r1[0]);
        if (blockIdx.x == 0) {
            float tau = s_r3[0] * (1.5f / 512.0f) + 1e-6f;
            float thr = s_r2[0] - 2.0f * tau;
            if (tid == 0) s_cnt = 0;
            __syncthreads();
            for (int i = tid; i < V; i += NT) {
                if (g_raw[i] >= thr) {
                    int p = atomicAdd(&s_cnt, 1);
                    if (p < 64) s_cand[p] = i;
                }
            }
            __syncthreads();
            int nc = min(s_cnt, 64);
            const float* h2p = g_hbuf[cur ^ 1];
            for (int c = wid; c < nc; c += NWPB) {
                int v = s_cand[c];
                float d = dotH_lane(W_out + (size_t)v * H, h2p, lane);
                d = wred(d);
                if (lane == 0)
                    s_cpk[c] = (((unsigned long long)f2mono(d + b_out[v])) << 32)
                             | (unsigned)(0xFFFFFFFFu - (unsigned)v);
            }
            __syncthreads();
            if (tid == 0) {
                unsigned long long best = 0ull;
                for (int c = 0; c < nc; c++) if (s_cpk[c] > best) best = s_cpk[c];
                int nxt = (int)(0xFFFFFFFFu - (unsigned)(best & 0xFFFFFFFFull));
                toks_out[L - 1] = (float)(done ? tok : nxt);
            }
        }
        for (int i = blockIdx.x * NT + tid; i < V; i += nblk * NT)
            logits_out[(long long)(L - 1) * V + i] = g_raw[i] - logZ;
    }
}

// ---------------- host launch ----------------
extern "C" void kernel_launch(void* const* d_in, const int* in_sizes, int n_in,
                              void* d_out, int out_size) {
    const int* qids      = (const int*)d_in[0];
    const int* cids      = (const int*)d_in[1];
    const float* enc_emb = (const float*)d_in[2];
    const float* enc_Wih = (const float*)d_in[3];
    const float* enc_Whh = (const float*)d_in[4];
    const float* enc_bih = (const float*)d_in[5];
    const float* enc_bhh = (const float*)d_in[6];
    const float* dec_emb = (const float*)d_in[7];
    const float* W_attn  = (const float*)d_in[8];
    const float* b_attn  = (const float*)d_in[9];
    const float* W_comb  = (const float*)d_in[10];
    const float* b_comb  = (const float*)d_in[11];
    const float* dW_ih   = (const float*)d_in[12];
    const float* dW_hh   = (const float*)d_in[13];
    const float* db_ih   = (const float*)d_in[14];
    const float* db_hh   = (const float*)d_in[15];
    const float* W_out   = (const float*)d_in[16];
    const float* b_out   = (const float*)d_in[17];

    float* out        = (float*)d_out;
    float* logits_out = out;
    float* attns_out  = out + (long long)L * V;
    float* toks_out   = attns_out + L * L;

    int dev = 0, sms = 148;
    cudaGetDevice(&dev);
    cudaDeviceGetAttribute(&sms, cudaDevAttrMultiProcessorCount, dev);
    int nblk = sms;
    if (nblk > 256) nblk = 256;
    if (nblk < 64) nblk = 64;   // M phase needs 64 blocks

    k_init<<<1, 1024>>>();
    k_prep<<<(V * H) / (8 * 256), 256>>>(W_out);
    k_gather<<<E * L, 256>>>(qids, cids, enc_emb);
    k_gi2<<<E * 48 * 2, 256>>>(enc_Wih);
    k_all<<<nblk, NT>>>(enc_Whh, enc_bih, enc_bhh, dec_emb, W_attn, b_attn,
                        W_comb, b_comb, dW_ih, dW_hh, db_ih, db_hh, W_out, b_out,
                        logits_out, attns_out, toks_out, nblk);
}